// round 8
// baseline (speedup 1.0000x reference)
#include <cuda_runtime.h>
#include <math.h>

// Problem constants
#define BB   64      // batch
#define NN   512     // nodes
#define RR   64      // r' (RP)
#define FEATD 256    // node features
#define EMBD 128     // embedding
#define TT   8       // MAX_WALK_LEN
#define D0   512     // MLP width (RR*TT)

// ---------------------------------------------------------------------------
// Device scratch (no cudaMalloc allowed)
// ---------------------------------------------------------------------------
__device__ float        g_M[RR * FEATD];             // Wv @ W  [64,256]
__device__ float        g_F1[BB * RR * NN];          // F1      [B,64,512]
__device__ float        g_FnA[BB * RR * NN];         // ping
__device__ float        g_FnB[BB * RR * NN];         // pong
__device__ unsigned int g_adjp[BB * NN * (NN / 32)]; // packed adjacency bits [B][m][n/32]
__device__ float        g_gpart[BB * TT * 2 * RR];   // gate partials per (b,t,tile,r)

// ---------------------------------------------------------------------------
// K0: pack adjacency: bit n of g_adjp[b][m][w] = (adj[b][n][m] != 0), n = w*32+j
// ---------------------------------------------------------------------------
__global__ void k_pack_adj(const int* __restrict__ adj) {
    int b  = blockIdx.y;
    int w  = blockIdx.x & 15;
    int mt = blockIdx.x >> 4;
    int m  = mt * 256 + threadIdx.x;
    const int* base = adj + ((size_t)b * NN + w * 32) * NN + m;
    unsigned int word = 0;
#pragma unroll
    for (int j = 0; j < 32; j++)
        word |= (base[j * NN] != 0 ? 1u : 0u) << j;
    g_adjp[(b * NN + m) * (NN / 32) + w] = word;
}

// ---------------------------------------------------------------------------
// K1: M = Wv[64,128] @ W[128,256]
// ---------------------------------------------------------------------------
__global__ void k_M(const float* __restrict__ Wv, const float* __restrict__ W) {
    int idx = blockIdx.x * 256 + threadIdx.x;
    int r = idx >> 8, c = idx & 255;
    float a = 0.f;
#pragma unroll 4
    for (int e = 0; e < EMBD; e++)
        a += Wv[r * EMBD + e] * W[e * FEATD + c];
    g_M[r * FEATD + c] = a;
}

// ---------------------------------------------------------------------------
// K2: F1[b,:,m] = sigmoid(M @ attr[b,m,:]) ; also gate_0 partials
// grid (2, 64), block 256, one column per thread
// ---------------------------------------------------------------------------
#define SM_F1 ((RR * FEATD + RR * RR + 8 * RR) * 4)

__global__ void __launch_bounds__(256, 1)
k_F1(const float* __restrict__ attr, const float* __restrict__ Wg) {
    extern __shared__ float sm[];
    float* smM  = sm;                   // [64][256]
    float* smWg = sm + RR * FEATD;      // [64][64]
    float* smG  = smWg + RR * RR;       // [8][64]

    int b = blockIdx.y, tile = blockIdx.x, tid = threadIdx.x;

    {
        const float4* s = (const float4*)g_M;
        float4* d = (float4*)smM;
        for (int i = tid; i < RR * FEATD / 4; i += 256) d[i] = s[i];
        const float4* s2 = (const float4*)Wg;
        float4* d2 = (float4*)smWg;
        for (int i = tid; i < RR * RR / 4; i += 256) d2[i] = s2[i];
    }
    __syncthreads();

    int m = tile * 256 + tid;
    float acc[RR];
#pragma unroll
    for (int r = 0; r < RR; r++) acc[r] = 0.f;

    const float4* arow = (const float4*)(attr + ((size_t)b * NN + m) * FEATD);
#pragma unroll 1
    for (int k4 = 0; k4 < FEATD / 4; k4++) {
        float4 a = __ldg(&arow[k4]);
        const float4* mc = (const float4*)smM + k4;
#pragma unroll
        for (int r = 0; r < RR; r++) {
            float4 w = mc[r * (FEATD / 4)];
            acc[r] += a.x * w.x + a.y * w.y + a.z * w.z + a.w * w.w;
        }
    }

#pragma unroll
    for (int r = 0; r < RR; r++) {
        float v = 1.f / (1.f + __expf(-acc[r]));
        acc[r] = v;
        g_F1[((size_t)b * RR + r) * NN + m] = v;
    }

    int lane = tid & 31, wrp = tid >> 5;
#pragma unroll 1
    for (int r = 0; r < RR; r++) {
        const float4* wr = (const float4*)(smWg + r * RR);
        float g = 0.f;
#pragma unroll
        for (int s4 = 0; s4 < RR / 4; s4++) {
            float4 w = wr[s4];
            g += w.x * acc[s4 * 4] + w.y * acc[s4 * 4 + 1] +
                 w.z * acc[s4 * 4 + 2] + w.w * acc[s4 * 4 + 3];
        }
        g = 1.f / (1.f + __expf(-g));
#pragma unroll
        for (int o = 16; o > 0; o >>= 1) g += __shfl_xor_sync(0xffffffffu, g, o);
        if (lane == 0) smG[wrp * RR + r] = g;
    }
    __syncthreads();
    if (tid < RR) {
        float tot = 0.f;
#pragma unroll
        for (int w = 0; w < 8; w++) tot += smG[w * RR + tid];
        g_gpart[((b * TT + 0) * 2 + tile) * RR + tid] = tot;
    }
}

// ---------------------------------------------------------------------------
// K3: one walk iteration (masked attention) + gate
// grid (2, 64), block 256: 2 threads per column (interleaved rows r = s+2i,
// stride 520 == 8 mod 32 -> the two slices hit disjoint bank quads), TWO
// column passes of 128 columns each (Fn tile loaded once). 255-reg budget:
// wwf2 pre-packed (no per-chunk dup movs), acc2 packed over key parity
// (halves acc FMA count), rows 0..15's even-keys cached across score->acc.
// Direct exp (validated): masked keys get p = 0 exactly.
// Pass-0 output staged in smOut0; smFnP overwritten only after a block-wide
// sync at the end of pass 1 (pass-1 scores need the full old Fn).
// ---------------------------------------------------------------------------
#define RSTRIDE 520
#define WSTRIDE 72
#define OSTRIDE 132
#define SM_ITER ((64 * RSTRIDE + 64 * WSTRIDE + RR * RR + 8 * RR + 64 * OSTRIDE) * 4 + 256 * 16 * 4)

__global__ void __launch_bounds__(256, 1)
k_iter(const float* __restrict__ Ww, const float* __restrict__ Wg, int t) {
    extern __shared__ float sm[];
    float*        smFnP  = sm;                                // [64][520]
    float*        smWwP  = sm + 64 * RSTRIDE;                 // [sp][72] permuted
    float*        smWg   = smWwP + 64 * WSTRIDE;              // [r][s]
    unsigned int* smAdj  = (unsigned int*)(smWg + RR * RR);   // [256][16]
    float*        smG    = (float*)(smAdj + 256 * 16);        // [8][64]
    float*        smOut0 = smG + 8 * RR;                      // [64][132]

    int b = blockIdx.y, tile = blockIdx.x, tid = threadIdx.x;

    const float* Fn_in  = (t == 1) ? g_F1 : ((t & 1) ? g_FnB : g_FnA);
    float*       Fn_out = (t & 1) ? g_FnA : g_FnB;

    {
        const float4* src = (const float4*)(Fn_in + (size_t)b * RR * NN);
        for (int idx = tid; idx < RR * NN / 4; idx += 256) {
            int row = idx >> 7, c4 = idx & 127;
            *((float4*)(smFnP + row * RSTRIDE) + c4) = src[idx];
        }
        // permuted Ww for interleaved slices: smWwP[sp*72 + (r&1)*36 + (r>>1)] = Ww[r][sp]
        for (int i = tid; i < RR * RR; i += 256) {
            int r = i >> 6, sp = i & 63;
            smWwP[sp * WSTRIDE + (r & 1) * 36 + (r >> 1)] = Ww[i];
        }
        const float4* s3 = (const float4*)Wg;
        float4* d3 = (float4*)smWg;
        for (int i = tid; i < RR * RR / 4; i += 256) d3[i] = s3[i];
        const uint4* s4p = (const uint4*)(g_adjp + ((size_t)b * NN + tile * 256) * 16);
        uint4* d4 = (uint4*)smAdj;
        for (int i = tid; i < 256 * 16 / 4; i += 256) d4[i] = s4p[i];
    }
    __syncthreads();

    int s  = tid & 1;          // slice: rows r = s + 2i
    int cg = tid >> 1;         // column group 0..127

#pragma unroll 1
    for (int pass = 0; pass < 2; pass++) {
        int ml = pass * 128 + cg;      // local column 0..255
        int m  = tile * 256 + ml;

        // ---- wwf[i] = sum_s' Ww[s+2i][s'] * Fn[s'][m]
        float wwf[32];
#pragma unroll
        for (int i = 0; i < 32; i++) wwf[i] = 0.f;
#pragma unroll 1
        for (int sp = 0; sp < 64; sp++) {
            float fs = smFnP[sp * RSTRIDE + m];
            const float4* wq = (const float4*)(smWwP + sp * WSTRIDE + s * 36);
#pragma unroll
            for (int q = 0; q < 8; q++) {
                float4 w = wq[q];
                wwf[q*4+0] += w.x * fs;
                wwf[q*4+1] += w.y * fs;
                wwf[q*4+2] += w.z * fs;
                wwf[q*4+3] += w.w * fs;
            }
        }
        // pre-pack duplicated query (kills the per-chunk mov.b64 dups)
        unsigned long long wwf2[32];
#pragma unroll
        for (int i = 0; i < 32; i++)
            asm("mov.b64 %0, {%1, %1};" : "=l"(wwf2[i]) : "f"(wwf[i]));

        // ---- masked attention, 8 keys per chunk, direct exp
        unsigned long long acc2[32];   // packed (even-key, odd-key) sums
#pragma unroll
        for (int i = 0; i < 32; i++) acc2[i] = 0ull;
        float dn = 0.f;
        unsigned int aw = 0;
        const unsigned int* myadj = smAdj + ml * 16;
        const ulonglong2* frows = (const ulonglong2*)(smFnP + s * RSTRIDE);

#pragma unroll 1
        for (int n0 = 0; n0 < NN; n0 += 8) {
            if ((n0 & 31) == 0) aw = myadj[n0 >> 5];

            const ulonglong2* fr = frows + (n0 >> 2);   // row step = 260 ul2

            unsigned long long s01 = 0ull, s23 = 0ull, s45 = 0ull, s67 = 0ull;
            ulonglong2 ca[16];   // cache rows 0..15 keys n0..n3 across passes
#pragma unroll
            for (int i = 0; i < 16; i++) {
                ca[i] = fr[i * 260];
                ulonglong2 fb = fr[i * 260 + 1];
                asm("fma.rn.f32x2 %0,%1,%2,%0;" : "+l"(s01) : "l"(ca[i].x), "l"(wwf2[i]));
                asm("fma.rn.f32x2 %0,%1,%2,%0;" : "+l"(s23) : "l"(ca[i].y), "l"(wwf2[i]));
                asm("fma.rn.f32x2 %0,%1,%2,%0;" : "+l"(s45) : "l"(fb.x),    "l"(wwf2[i]));
                asm("fma.rn.f32x2 %0,%1,%2,%0;" : "+l"(s67) : "l"(fb.y),    "l"(wwf2[i]));
            }
#pragma unroll
            for (int i = 16; i < 32; i++) {
                ulonglong2 fa = fr[i * 260];
                ulonglong2 fb = fr[i * 260 + 1];
                asm("fma.rn.f32x2 %0,%1,%2,%0;" : "+l"(s01) : "l"(fa.x), "l"(wwf2[i]));
                asm("fma.rn.f32x2 %0,%1,%2,%0;" : "+l"(s23) : "l"(fa.y), "l"(wwf2[i]));
                asm("fma.rn.f32x2 %0,%1,%2,%0;" : "+l"(s45) : "l"(fb.x), "l"(wwf2[i]));
                asm("fma.rn.f32x2 %0,%1,%2,%0;" : "+l"(s67) : "l"(fb.y), "l"(wwf2[i]));
            }
            // combine with pair partner (other slice)
            {
                unsigned long long o0 = __shfl_xor_sync(0xffffffffu, s01, 1);
                unsigned long long o1 = __shfl_xor_sync(0xffffffffu, s23, 1);
                unsigned long long o2 = __shfl_xor_sync(0xffffffffu, s45, 1);
                unsigned long long o3 = __shfl_xor_sync(0xffffffffu, s67, 1);
                asm("add.rn.f32x2 %0, %0, %1;" : "+l"(s01) : "l"(o0));
                asm("add.rn.f32x2 %0, %0, %1;" : "+l"(s23) : "l"(o1));
                asm("add.rn.f32x2 %0, %0, %1;" : "+l"(s45) : "l"(o2));
                asm("add.rn.f32x2 %0, %0, %1;" : "+l"(s67) : "l"(o3));
            }
            float s0, s1, s2, s3, s4, s5, s6, s7;
            asm("mov.b64 {%0, %1}, %2;" : "=f"(s0), "=f"(s1) : "l"(s01));
            asm("mov.b64 {%0, %1}, %2;" : "=f"(s2), "=f"(s3) : "l"(s23));
            asm("mov.b64 {%0, %1}, %2;" : "=f"(s4), "=f"(s5) : "l"(s45));
            asm("mov.b64 {%0, %1}, %2;" : "=f"(s6), "=f"(s7) : "l"(s67));

            unsigned int bits = aw >> (n0 & 31);
            float p0 = (bits & 1u)   ? __expf(s0) : 0.f;
            float p1 = (bits & 2u)   ? __expf(s1) : 0.f;
            float p2 = (bits & 4u)   ? __expf(s2) : 0.f;
            float p3 = (bits & 8u)   ? __expf(s3) : 0.f;
            float p4 = (bits & 16u)  ? __expf(s4) : 0.f;
            float p5 = (bits & 32u)  ? __expf(s5) : 0.f;
            float p6 = (bits & 64u)  ? __expf(s6) : 0.f;
            float p7 = (bits & 128u) ? __expf(s7) : 0.f;
            dn += ((p0 + p1) + (p2 + p3)) + ((p4 + p5) + (p6 + p7));

            unsigned long long pp01, pp23, pp45, pp67;
            asm("mov.b64 %0, {%1, %2};" : "=l"(pp01) : "f"(p0), "f"(p1));
            asm("mov.b64 %0, {%1, %2};" : "=l"(pp23) : "f"(p2), "f"(p3));
            asm("mov.b64 %0, {%1, %2};" : "=l"(pp45) : "f"(p4), "f"(p5));
            asm("mov.b64 %0, {%1, %2};" : "=l"(pp67) : "f"(p6), "f"(p7));

#pragma unroll
            for (int i = 0; i < 16; i++) {
                ulonglong2 fb = fr[i * 260 + 1];
                asm("fma.rn.f32x2 %0,%1,%2,%0;" : "+l"(acc2[i]) : "l"(ca[i].x), "l"(pp01));
                asm("fma.rn.f32x2 %0,%1,%2,%0;" : "+l"(acc2[i]) : "l"(ca[i].y), "l"(pp23));
                asm("fma.rn.f32x2 %0,%1,%2,%0;" : "+l"(acc2[i]) : "l"(fb.x),    "l"(pp45));
                asm("fma.rn.f32x2 %0,%1,%2,%0;" : "+l"(acc2[i]) : "l"(fb.y),    "l"(pp67));
            }
#pragma unroll
            for (int i = 16; i < 32; i++) {
                ulonglong2 fa = fr[i * 260];
                ulonglong2 fb = fr[i * 260 + 1];
                asm("fma.rn.f32x2 %0,%1,%2,%0;" : "+l"(acc2[i]) : "l"(fa.x), "l"(pp01));
                asm("fma.rn.f32x2 %0,%1,%2,%0;" : "+l"(acc2[i]) : "l"(fa.y), "l"(pp23));
                asm("fma.rn.f32x2 %0,%1,%2,%0;" : "+l"(acc2[i]) : "l"(fb.x), "l"(pp45));
                asm("fma.rn.f32x2 %0,%1,%2,%0;" : "+l"(acc2[i]) : "l"(fb.y), "l"(pp67));
            }
        }

        // ---- epilogue
        float inv = 1.f / dn;
        const float* f1base = g_F1 + (size_t)b * RR * NN;
        float*       outb   = Fn_out + (size_t)b * RR * NN;

        if (pass == 0) {
            // stage pass-0 output in smOut0 (smFnP must stay intact for pass 1)
#pragma unroll
            for (int i = 0; i < 32; i++) {
                int r = s + 2 * i;
                float lo, hi;
                asm("mov.b64 {%0,%1}, %2;" : "=f"(lo), "=f"(hi) : "l"(acc2[i]));
                float v = (lo + hi) * inv * f1base[r * NN + m];
                outb[r * NN + m] = v;
                smOut0[r * OSTRIDE + cg] = v;
            }
        } else {
            __syncthreads();   // all pass-1 reads of old smFnP complete
#pragma unroll
            for (int i = 0; i < 32; i++) {
                int r = s + 2 * i;
                float lo, hi;
                asm("mov.b64 {%0,%1}, %2;" : "=f"(lo), "=f"(hi) : "l"(acc2[i]));
                float v = (lo + hi) * inv * f1base[r * NN + m];
                outb[r * NN + m] = v;
                smFnP[r * RSTRIDE + ml] = v;                       // cols 128..255
                smFnP[r * RSTRIDE + cg] = smOut0[r * OSTRIDE + cg]; // cols 0..127
            }
        }
    }
    __syncthreads();

    // ---- gate_t = sum_m sigmoid(Wg @ Fn_new[:,m]) ; one column per thread
    {
        float f[RR];
#pragma unroll
        for (int r = 0; r < RR; r++) f[r] = smFnP[r * RSTRIDE + tid];

        int lane = tid & 31, wrp = tid >> 5;
#pragma unroll 1
        for (int r = 0; r < RR; r++) {
            const float4* wr = (const float4*)(smWg + r * RR);
            float g = 0.f;
#pragma unroll
            for (int s4 = 0; s4 < 16; s4++) {
                float4 w = wr[s4];
                g += w.x * f[s4*4] + w.y * f[s4*4+1] +
                     w.z * f[s4*4+2] + w.w * f[s4*4+3];
            }
            g = 1.f / (1.f + __expf(-g));
#pragma unroll
            for (int o = 16; o > 0; o >>= 1) g += __shfl_xor_sync(0xffffffffu, g, o);
            if (lane == 0) smG[wrp * RR + r] = g;
        }
        __syncthreads();
        if (tid < RR) {
            float tot = 0.f;
#pragma unroll
            for (int w = 0; w < 8; w++) tot += smG[w * RR + tid];
            g_gpart[((b * TT + t) * 2 + tile) * RR + tid] = tot;
        }
    }
}

// ---------------------------------------------------------------------------
// K4: assemble fT, L2-normalize, 4-layer MLP. grid 16 (4 batches/CTA), block 256
// ---------------------------------------------------------------------------
__device__ __forceinline__ void mlp_layer(const float (*hin)[D0], float (*hout)[D0],
                                          const float* __restrict__ W,
                                          const float* __restrict__ bias,
                                          int Din, int Dout, int tid) {
    for (int i = tid; i < Dout; i += 256) {
        const float4* wr = (const float4*)(W + (size_t)i * Din);
        float a0 = 0.f, a1 = 0.f, a2 = 0.f, a3 = 0.f;
#pragma unroll 4
        for (int k4 = 0; k4 < Din / 4; k4++) {
            float4 w = __ldg(&wr[k4]);
            float4 x0 = *(const float4*)&hin[0][k4 * 4];
            float4 x1 = *(const float4*)&hin[1][k4 * 4];
            float4 x2 = *(const float4*)&hin[2][k4 * 4];
            float4 x3 = *(const float4*)&hin[3][k4 * 4];
            a0 += w.x * x0.x + w.y * x0.y + w.z * x0.z + w.w * x0.w;
            a1 += w.x * x1.x + w.y * x1.y + w.z * x1.z + w.w * x1.w;
            a2 += w.x * x2.x + w.y * x2.y + w.z * x2.z + w.w * x2.w;
            a3 += w.x * x3.x + w.y * x3.y + w.z * x3.z + w.w * x3.w;
        }
        float bi = bias[i];
        hout[0][i] = fmaxf(a0 + bi, 0.f);
        hout[1][i] = fmaxf(a1 + bi, 0.f);
        hout[2][i] = fmaxf(a2 + bi, 0.f);
        hout[3][i] = fmaxf(a3 + bi, 0.f);
    }
}

__global__ void __launch_bounds__(256, 1)
k_mlp(const float* __restrict__ W0, const float* __restrict__ b0,
      const float* __restrict__ W1, const float* __restrict__ b1,
      const float* __restrict__ W2, const float* __restrict__ b2,
      const float* __restrict__ W3, const float* __restrict__ b3,
      float* __restrict__ out) {
    __shared__ float hA[4][D0];
    __shared__ float hB[4][D0];
    __shared__ float smScale[4];
    int tid = threadIdx.x;
    int bbase = blockIdx.x * 4;

    for (int idx = tid; idx < 4 * D0; idx += 256) {
        int bb = idx >> 9, j = idx & 511, t = j >> 6, r = j & 63;
        int g0 = (((bbase + bb) * TT + t) * 2 + 0) * RR + r;
        hA[bb][j] = g_gpart[g0] + g_gpart[g0 + RR];
    }
    __syncthreads();

    int lane = tid & 31, wrp = tid >> 5;
    if (wrp < 4) {
        float ss = 0.f;
        for (int i = lane; i < D0; i += 32) { float v = hA[wrp][i]; ss += v * v; }
#pragma unroll
        for (int o = 16; o > 0; o >>= 1) ss += __shfl_xor_sync(0xffffffffu, ss, o);
        if (lane == 0) smScale[wrp] = 1.f / fmaxf(sqrtf(ss), 1e-12f);
    }
    __syncthreads();
    for (int idx = tid; idx < 4 * D0; idx += 256) {
        int bb = idx >> 9;
        hA[bb][idx & 511] *= smScale[bb];
    }
    __syncthreads();

    mlp_layer(hA, hB, W0, b0, 512, 512, tid); __syncthreads();
    mlp_layer(hB, hA, W1, b1, 512, 512, tid); __syncthreads();
    mlp_layer(hA, hB, W2, b2, 512, 256, tid); __syncthreads();

    for (int i = tid; i < 128; i += 256) {
        const float4* wr = (const float4*)(W3 + (size_t)i * 256);
        float a0 = 0.f, a1 = 0.f, a2 = 0.f, a3 = 0.f;
#pragma unroll 4
        for (int k4 = 0; k4 < 64; k4++) {
            float4 w = __ldg(&wr[k4]);
            float4 x0 = *(const float4*)&hB[0][k4 * 4];
            float4 x1 = *(const float4*)&hB[1][k4 * 4];
            float4 x2 = *(const float4*)&hB[2][k4 * 4];
            float4 x3 = *(const float4*)&hB[3][k4 * 4];
            a0 += w.x * x0.x + w.y * x0.y + w.z * x0.z + w.w * x0.w;
            a1 += w.x * x1.x + w.y * x1.y + w.z * x1.z + w.w * x1.w;
            a2 += w.x * x2.x + w.y * x2.y + w.z * x2.z + w.w * x2.w;
            a3 += w.x * x3.x + w.y * x3.y + w.z * x3.z + w.w * x3.w;
        }
        float bi = b3[i];
        out[(bbase + 0) * 128 + i] = a0 + bi;
        out[(bbase + 1) * 128 + i] = a1 + bi;
        out[(bbase + 2) * 128 + i] = a2 + bi;
        out[(bbase + 3) * 128 + i] = a3 + bi;
    }
}

// ---------------------------------------------------------------------------
// launch
// ---------------------------------------------------------------------------
extern "C" void kernel_launch(void* const* d_in, const int* in_sizes, int n_in,
                              void* d_out, int out_size) {
    const float* attr = (const float*)d_in[0];
    const int*   adj  = (const int*)d_in[1];
    const float* W    = (const float*)d_in[2];
    const float* Wv   = (const float*)d_in[3];
    const float* Ww   = (const float*)d_in[4];
    const float* Wg   = (const float*)d_in[5];
    const float* W0   = (const float*)d_in[6];
    const float* b0   = (const float*)d_in[7];
    const float* W1   = (const float*)d_in[8];
    const float* b1   = (const float*)d_in[9];
    const float* W2   = (const float*)d_in[10];
    const float* b2   = (const float*)d_in[11];
    const float* W3   = (const float*)d_in[12];
    const float* b3   = (const float*)d_in[13];
    float* out = (float*)d_out;

    cudaFuncSetAttribute(k_F1,   cudaFuncAttributeMaxDynamicSharedMemorySize, SM_F1);
    cudaFuncSetAttribute(k_iter, cudaFuncAttributeMaxDynamicSharedMemorySize, SM_ITER);

    k_pack_adj<<<dim3(32, 64), 256>>>(adj);
    k_M<<<64, 256>>>(Wv, W);
    k_F1<<<dim3(2, 64), 256, SM_F1>>>(attr, Wg);
    for (int t = 1; t < TT; t++)
        k_iter<<<dim3(2, 64), 256, SM_ITER>>>(Ww, Wg, t);
    k_mlp<<<16, 256>>>(W0, b0, W1, b1, W2, b2, W3, b3, out);
}

// round 10
// speedup vs baseline: 1.0078x; 1.0078x over previous
#include <cuda_runtime.h>
#include <math.h>

// Problem constants
#define BB   64      // batch
#define NN   512     // nodes
#define RR   64      // r' (RP)
#define FEATD 256    // node features
#define EMBD 128     // embedding
#define TT   8       // MAX_WALK_LEN
#define D0   512     // MLP width (RR*TT)

typedef unsigned long long ull;

// ---------------------------------------------------------------------------
// Device scratch (no cudaMalloc allowed)
// g_F1P / g_FnA / g_FnB are ROW-PAIR-PACKED: [B][32][512][2] floats, i.e.
// pair i holds rows (2i, 2i+1) interleaved per column.
// ---------------------------------------------------------------------------
__device__ float        g_M[RR * FEATD];             // Wv @ W  [64,256]
__device__ float        g_F1P[BB * RR * NN];         // F1 pair-packed
__device__ float        g_FnA[BB * RR * NN];         // ping (pair-packed)
__device__ float        g_FnB[BB * RR * NN];         // pong (pair-packed)
__device__ unsigned int g_adjp[BB * NN * (NN / 32)]; // packed adjacency bits
__device__ float        g_gpart[BB * TT * 2 * RR];   // gate partials

// ---------------------------------------------------------------------------
// K0: pack adjacency: bit n of g_adjp[b][m][w] = (adj[b][n][m] != 0)
// ---------------------------------------------------------------------------
__global__ void k_pack_adj(const int* __restrict__ adj) {
    int b  = blockIdx.y;
    int w  = blockIdx.x & 15;
    int mt = blockIdx.x >> 4;
    int m  = mt * 256 + threadIdx.x;
    const int* base = adj + ((size_t)b * NN + w * 32) * NN + m;
    unsigned int word = 0;
#pragma unroll
    for (int j = 0; j < 32; j++)
        word |= (base[j * NN] != 0 ? 1u : 0u) << j;
    g_adjp[(b * NN + m) * (NN / 32) + w] = word;
}

// ---------------------------------------------------------------------------
// K1: M = Wv[64,128] @ W[128,256]
// ---------------------------------------------------------------------------
__global__ void k_M(const float* __restrict__ Wv, const float* __restrict__ W) {
    int idx = blockIdx.x * 256 + threadIdx.x;
    int r = idx >> 8, c = idx & 255;
    float a = 0.f;
#pragma unroll 4
    for (int e = 0; e < EMBD; e++)
        a += Wv[r * EMBD + e] * W[e * FEATD + c];
    g_M[r * FEATD + c] = a;
}

// ---------------------------------------------------------------------------
// K2: F1[b,:,m] = sigmoid(M @ attr[b,m,:]) ; also gate_0 partials
// grid (2, 64), block 256, one column per thread. Writes F1 pair-packed.
// ---------------------------------------------------------------------------
#define SM_F1 ((RR * FEATD + RR * RR + 8 * RR) * 4)

__global__ void __launch_bounds__(256, 1)
k_F1(const float* __restrict__ attr, const float* __restrict__ Wg) {
    extern __shared__ float sm[];
    float* smM  = sm;                   // [64][256]
    float* smWg = sm + RR * FEATD;      // [64][64]
    float* smG  = smWg + RR * RR;       // [8][64]

    int b = blockIdx.y, tile = blockIdx.x, tid = threadIdx.x;

    {
        const float4* s = (const float4*)g_M;
        float4* d = (float4*)smM;
        for (int i = tid; i < RR * FEATD / 4; i += 256) d[i] = s[i];
        const float4* s2 = (const float4*)Wg;
        float4* d2 = (float4*)smWg;
        for (int i = tid; i < RR * RR / 4; i += 256) d2[i] = s2[i];
    }
    __syncthreads();

    int m = tile * 256 + tid;
    float acc[RR];
#pragma unroll
    for (int r = 0; r < RR; r++) acc[r] = 0.f;

    const float4* arow = (const float4*)(attr + ((size_t)b * NN + m) * FEATD);
#pragma unroll 1
    for (int k4 = 0; k4 < FEATD / 4; k4++) {
        float4 a = __ldg(&arow[k4]);
        const float4* mc = (const float4*)smM + k4;
#pragma unroll
        for (int r = 0; r < RR; r++) {
            float4 w = mc[r * (FEATD / 4)];
            acc[r] += a.x * w.x + a.y * w.y + a.z * w.z + a.w * w.w;
        }
    }

    ull* f1out = (ull*)(g_F1P + (size_t)b * RR * NN);
#pragma unroll
    for (int i = 0; i < RR / 2; i++) {
        float v0 = 1.f / (1.f + __expf(-acc[2 * i]));
        float v1 = 1.f / (1.f + __expf(-acc[2 * i + 1]));
        acc[2 * i] = v0;
        acc[2 * i + 1] = v1;
        ull pk;
        asm("mov.b64 %0, {%1, %2};" : "=l"(pk) : "f"(v0), "f"(v1));
        f1out[i * NN + m] = pk;
    }

    int lane = tid & 31, wrp = tid >> 5;
#pragma unroll 1
    for (int r = 0; r < RR; r++) {
        const float4* wr = (const float4*)(smWg + r * RR);
        float g = 0.f;
#pragma unroll
        for (int s4 = 0; s4 < RR / 4; s4++) {
            float4 w = wr[s4];
            g += w.x * acc[s4 * 4] + w.y * acc[s4 * 4 + 1] +
                 w.z * acc[s4 * 4 + 2] + w.w * acc[s4 * 4 + 3];
        }
        g = 1.f / (1.f + __expf(-g));
#pragma unroll
        for (int o = 16; o > 0; o >>= 1) g += __shfl_xor_sync(0xffffffffu, g, o);
        if (lane == 0) smG[wrp * RR + r] = g;
    }
    __syncthreads();
    if (tid < RR) {
        float tot = 0.f;
#pragma unroll
        for (int w = 0; w < 8; w++) tot += smG[w * RR + tid];
        g_gpart[((b * TT + 0) * 2 + tile) * RR + tid] = tot;
    }
}

// ---------------------------------------------------------------------------
// K3: one walk iteration (masked attention) + gate
// grid (2, 64), block 512. Fn stored ROW-PAIR-PACKED in smem:
//   smF[pair i][n][2] = (Fn[2i][n], Fn[2i+1][n]), pair stride 1028 floats.
// Thread s (tid&1) owns pairs i = 2j+s (j<16); 2 threads per column.
// BOTH passes are fma.rn.f32x2. Direct exp (validated): masked keys p = 0.
// smF is indexed by GLOBAL column (0..511); epilogue restage AND gate reads
// both use the global column m (R9 bug: gate read local ml -> stale cols for
// tile 1).
// ---------------------------------------------------------------------------
#define PSTR 1028
#define WSTRIDE 72
#define SM_ITER ((32 * PSTR + 64 * WSTRIDE + RR * RR + 16 * RR) * 4 + 256 * 16 * 4)

__global__ void __launch_bounds__(512, 1)
k_iter(const float* __restrict__ Ww, const float* __restrict__ Wg, int t) {
    extern __shared__ float sm[];
    float*        smF   = sm;                                // [32][1028]
    float*        smWwP = sm + 32 * PSTR;                    // [sp][72]
    float*        smWg  = smWwP + 64 * WSTRIDE;              // [r][s]
    unsigned int* smAdj = (unsigned int*)(smWg + RR * RR);   // [256][16]
    float*        smG   = (float*)(smAdj + 256 * 16);        // [16][64]

    int b = blockIdx.y, tile = blockIdx.x, tid = threadIdx.x;

    const float* Fn_in  = (t == 1) ? g_F1P : ((t & 1) ? g_FnB : g_FnA);
    float*       Fn_out = (t & 1) ? g_FnA : g_FnB;

    {
        // stage pair-packed Fn: global [32][1024] -> smem rows stride 1028
        const float4* src = (const float4*)(Fn_in + (size_t)b * RR * NN);
        for (int idx = tid; idx < RR * NN / 4; idx += 512) {
            int ip = idx >> 8, c4 = idx & 255;
            *((float4*)(smF + ip * PSTR) + c4) = src[idx];
        }
        // permuted Ww: smWwP[sp*72 + ss*36 + j*2 + e] = Ww[4j + 2ss + e][sp]
        for (int i = tid; i < RR * RR; i += 512) {
            int r = i >> 6, sp = i & 63;
            int e = r & 1, pr = r >> 1;
            int ss = pr & 1, j = pr >> 1;
            smWwP[sp * WSTRIDE + ss * 36 + j * 2 + e] = Ww[i];
        }
        const float4* s3 = (const float4*)Wg;
        float4* d3 = (float4*)smWg;
        for (int i = tid; i < RR * RR / 4; i += 512) d3[i] = s3[i];
        const uint4* s4p = (const uint4*)(g_adjp + ((size_t)b * NN + tile * 256) * 16);
        uint4* d4 = (uint4*)smAdj;
        for (int i = tid; i < 256 * 16 / 4; i += 512) d4[i] = s4p[i];
    }
    __syncthreads();

    int s  = tid & 1;          // slice: pairs i = 2j+s
    int ml = tid >> 1;         // local column 0..255
    int m  = tile * 256 + ml;  // GLOBAL column

    // ---- wwf2[j] = packed (wwf[4j+2s], wwf[4j+2s+1])
    ull wwf2[16];
#pragma unroll
    for (int j = 0; j < 16; j++) wwf2[j] = 0ull;
#pragma unroll 1
    for (int sp = 0; sp < 64; sp++) {
        float fs = smF[(sp >> 1) * PSTR + m * 2 + (sp & 1)];
        ull fsd;
        asm("mov.b64 %0, {%1, %1};" : "=l"(fsd) : "f"(fs));
        const ulonglong2* wq = (const ulonglong2*)(smWwP + sp * WSTRIDE + s * 36);
#pragma unroll
        for (int q = 0; q < 8; q++) {
            ulonglong2 wp = wq[q];
            asm("fma.rn.f32x2 %0, %1, %2, %0;" : "+l"(wwf2[2*q])   : "l"(wp.x), "l"(fsd));
            asm("fma.rn.f32x2 %0, %1, %2, %0;" : "+l"(wwf2[2*q+1]) : "l"(wp.y), "l"(fsd));
        }
    }

    // ---- masked attention, 8 keys per chunk, direct exp
    ull acc2[16];   // packed (acc[2i], acc[2i+1])
#pragma unroll
    for (int j = 0; j < 16; j++) acc2[j] = 0ull;
    float dn = 0.f;
    unsigned int aw = 0;
    const unsigned int* myadj = smAdj + ml * 16;
    const ulonglong2* frbase = (const ulonglong2*)smF + s * 257;  // pair s

#pragma unroll 1
    for (int n0 = 0; n0 < NN; n0 += 8) {
        if ((n0 & 31) == 0) aw = myadj[n0 >> 5];

        const ulonglong2* fr = frbase + (n0 >> 1);   // step per j: 514 ul2

        ull sc0 = 0ull, sc1 = 0ull, sc2 = 0ull, sc3 = 0ull;
        ull sc4 = 0ull, sc5 = 0ull, sc6 = 0ull, sc7 = 0ull;
#pragma unroll
        for (int j = 0; j < 16; j++) {
            const ulonglong2* rp = fr + j * 514;
            ulonglong2 A = rp[0], B = rp[1], C = rp[2], D = rp[3];
            ull w = wwf2[j];
            asm("fma.rn.f32x2 %0, %1, %2, %0;" : "+l"(sc0) : "l"(A.x), "l"(w));
            asm("fma.rn.f32x2 %0, %1, %2, %0;" : "+l"(sc1) : "l"(A.y), "l"(w));
            asm("fma.rn.f32x2 %0, %1, %2, %0;" : "+l"(sc2) : "l"(B.x), "l"(w));
            asm("fma.rn.f32x2 %0, %1, %2, %0;" : "+l"(sc3) : "l"(B.y), "l"(w));
            asm("fma.rn.f32x2 %0, %1, %2, %0;" : "+l"(sc4) : "l"(C.x), "l"(w));
            asm("fma.rn.f32x2 %0, %1, %2, %0;" : "+l"(sc5) : "l"(C.y), "l"(w));
            asm("fma.rn.f32x2 %0, %1, %2, %0;" : "+l"(sc6) : "l"(D.x), "l"(w));
            asm("fma.rn.f32x2 %0, %1, %2, %0;" : "+l"(sc7) : "l"(D.y), "l"(w));
        }
        // combine with pair partner (other slice)
        {
            ull o0 = __shfl_xor_sync(0xffffffffu, sc0, 1);
            ull o1 = __shfl_xor_sync(0xffffffffu, sc1, 1);
            ull o2 = __shfl_xor_sync(0xffffffffu, sc2, 1);
            ull o3 = __shfl_xor_sync(0xffffffffu, sc3, 1);
            asm("add.rn.f32x2 %0, %0, %1;" : "+l"(sc0) : "l"(o0));
            asm("add.rn.f32x2 %0, %0, %1;" : "+l"(sc1) : "l"(o1));
            asm("add.rn.f32x2 %0, %0, %1;" : "+l"(sc2) : "l"(o2));
            asm("add.rn.f32x2 %0, %0, %1;" : "+l"(sc3) : "l"(o3));
            ull o4 = __shfl_xor_sync(0xffffffffu, sc4, 1);
            ull o5 = __shfl_xor_sync(0xffffffffu, sc5, 1);
            ull o6 = __shfl_xor_sync(0xffffffffu, sc6, 1);
            ull o7 = __shfl_xor_sync(0xffffffffu, sc7, 1);
            asm("add.rn.f32x2 %0, %0, %1;" : "+l"(sc4) : "l"(o4));
            asm("add.rn.f32x2 %0, %0, %1;" : "+l"(sc5) : "l"(o5));
            asm("add.rn.f32x2 %0, %0, %1;" : "+l"(sc6) : "l"(o6));
            asm("add.rn.f32x2 %0, %0, %1;" : "+l"(sc7) : "l"(o7));
        }
        // horizontal (rows) + mask + exp
        unsigned int bits = aw >> (n0 & 31);
        float lo, hi, p0, p1, p2, p3, p4, p5, p6, p7;
        asm("mov.b64 {%0,%1}, %2;" : "=f"(lo), "=f"(hi) : "l"(sc0));
        p0 = (bits & 1u)   ? __expf(lo + hi) : 0.f;
        asm("mov.b64 {%0,%1}, %2;" : "=f"(lo), "=f"(hi) : "l"(sc1));
        p1 = (bits & 2u)   ? __expf(lo + hi) : 0.f;
        asm("mov.b64 {%0,%1}, %2;" : "=f"(lo), "=f"(hi) : "l"(sc2));
        p2 = (bits & 4u)   ? __expf(lo + hi) : 0.f;
        asm("mov.b64 {%0,%1}, %2;" : "=f"(lo), "=f"(hi) : "l"(sc3));
        p3 = (bits & 8u)   ? __expf(lo + hi) : 0.f;
        asm("mov.b64 {%0,%1}, %2;" : "=f"(lo), "=f"(hi) : "l"(sc4));
        p4 = (bits & 16u)  ? __expf(lo + hi) : 0.f;
        asm("mov.b64 {%0,%1}, %2;" : "=f"(lo), "=f"(hi) : "l"(sc5));
        p5 = (bits & 32u)  ? __expf(lo + hi) : 0.f;
        asm("mov.b64 {%0,%1}, %2;" : "=f"(lo), "=f"(hi) : "l"(sc6));
        p6 = (bits & 64u)  ? __expf(lo + hi) : 0.f;
        asm("mov.b64 {%0,%1}, %2;" : "=f"(lo), "=f"(hi) : "l"(sc7));
        p7 = (bits & 128u) ? __expf(lo + hi) : 0.f;
        dn += ((p0 + p1) + (p2 + p3)) + ((p4 + p5) + (p6 + p7));

        ull q0, q1, q2, q3, q4, q5, q6, q7;
        asm("mov.b64 %0, {%1, %1};" : "=l"(q0) : "f"(p0));
        asm("mov.b64 %0, {%1, %1};" : "=l"(q1) : "f"(p1));
        asm("mov.b64 %0, {%1, %1};" : "=l"(q2) : "f"(p2));
        asm("mov.b64 %0, {%1, %1};" : "=l"(q3) : "f"(p3));
        asm("mov.b64 %0, {%1, %1};" : "=l"(q4) : "f"(p4));
        asm("mov.b64 %0, {%1, %1};" : "=l"(q5) : "f"(p5));
        asm("mov.b64 %0, {%1, %1};" : "=l"(q6) : "f"(p6));
        asm("mov.b64 %0, {%1, %1};" : "=l"(q7) : "f"(p7));

#pragma unroll
        for (int j = 0; j < 16; j++) {
            const ulonglong2* rp = fr + j * 514;
            ulonglong2 A = rp[0], B = rp[1], C = rp[2], D = rp[3];
            asm("fma.rn.f32x2 %0, %1, %2, %0;" : "+l"(acc2[j]) : "l"(A.x), "l"(q0));
            asm("fma.rn.f32x2 %0, %1, %2, %0;" : "+l"(acc2[j]) : "l"(A.y), "l"(q1));
            asm("fma.rn.f32x2 %0, %1, %2, %0;" : "+l"(acc2[j]) : "l"(B.x), "l"(q2));
            asm("fma.rn.f32x2 %0, %1, %2, %0;" : "+l"(acc2[j]) : "l"(B.y), "l"(q3));
            asm("fma.rn.f32x2 %0, %1, %2, %0;" : "+l"(acc2[j]) : "l"(C.x), "l"(q4));
            asm("fma.rn.f32x2 %0, %1, %2, %0;" : "+l"(acc2[j]) : "l"(C.y), "l"(q5));
            asm("fma.rn.f32x2 %0, %1, %2, %0;" : "+l"(acc2[j]) : "l"(D.x), "l"(q6));
            asm("fma.rn.f32x2 %0, %1, %2, %0;" : "+l"(acc2[j]) : "l"(D.y), "l"(q7));
        }
    }

    // ---- epilogue: scale, multiply by F1 (pair loads), write + restage
    float inv = 1.f / dn;
    __syncthreads();   // all reads of old smF complete before restaging
    const ull* f1p  = (const ull*)(g_F1P + (size_t)b * RR * NN);
    ull*       outp = (ull*)(Fn_out + (size_t)b * RR * NN);
#pragma unroll
    for (int j = 0; j < 16; j++) {
        int i = 2 * j + s;                 // pair index (rows 2i, 2i+1)
        ull f1u = f1p[i * NN + m];
        float f1e, f1o, ae, ao;
        asm("mov.b64 {%0,%1}, %2;" : "=f"(f1e), "=f"(f1o) : "l"(f1u));
        asm("mov.b64 {%0,%1}, %2;" : "=f"(ae),  "=f"(ao)  : "l"(acc2[j]));
        float v0 = ae * inv * f1e;
        float v1 = ao * inv * f1o;
        ull pk;
        asm("mov.b64 %0, {%1, %2};" : "=l"(pk) : "f"(v0), "f"(v1));
        outp[i * NN + m] = pk;
        ((ull*)smF)[i * 514 + m] = pk;     // GLOBAL column m
    }
    __syncthreads();

    // ---- gate_t = sum_m sigmoid(Wg @ Fn_new[:,m])
    // FIX: read this CTA's own columns at GLOBAL index m (R9 read local ml).
    int rb = (tid & 1) * 32;      // r-half for the gate dot
    float f[32];
#pragma unroll
    for (int i = 0; i < 32; i++) {
        int r = rb + i;
        f[i] = smF[(r >> 1) * PSTR + m * 2 + (r & 1)];
    }

    int lane = tid & 31, wrp = tid >> 5;
#pragma unroll 1
    for (int r = 0; r < RR; r++) {
        const float4* wr = (const float4*)(smWg + r * RR + rb);
        float g = 0.f;
#pragma unroll
        for (int s4 = 0; s4 < 8; s4++) {
            float4 w = wr[s4];
            g += w.x * f[s4*4] + w.y * f[s4*4+1] +
                 w.z * f[s4*4+2] + w.w * f[s4*4+3];
        }
        g += __shfl_xor_sync(0xffffffffu, g, 1);       // full dot for this column
        g = 1.f / (1.f + __expf(-g));
#pragma unroll
        for (int o = 2; o < 32; o <<= 1) g += __shfl_xor_sync(0xffffffffu, g, o);
        if (lane == 0) smG[wrp * RR + r] = g;          // 16 distinct columns per warp
    }
    __syncthreads();
    if (tid < RR) {
        float tot = 0.f;
#pragma unroll
        for (int w = 0; w < 16; w++) tot += smG[w * RR + tid];
        g_gpart[((b * TT + t) * 2 + tile) * RR + tid] = tot;
    }
}

// ---------------------------------------------------------------------------
// K4: assemble fT, L2-normalize, 4-layer MLP. grid 16 (4 batches/CTA), block 256
// ---------------------------------------------------------------------------
__device__ __forceinline__ void mlp_layer(const float (*hin)[D0], float (*hout)[D0],
                                          const float* __restrict__ W,
                                          const float* __restrict__ bias,
                                          int Din, int Dout, int tid) {
    for (int i = tid; i < Dout; i += 256) {
        const float4* wr = (const float4*)(W + (size_t)i * Din);
        float a0 = 0.f, a1 = 0.f, a2 = 0.f, a3 = 0.f;
#pragma unroll 4
        for (int k4 = 0; k4 < Din / 4; k4++) {
            float4 w = __ldg(&wr[k4]);
            float4 x0 = *(const float4*)&hin[0][k4 * 4];
            float4 x1 = *(const float4*)&hin[1][k4 * 4];
            float4 x2 = *(const float4*)&hin[2][k4 * 4];
            float4 x3 = *(const float4*)&hin[3][k4 * 4];
            a0 += w.x * x0.x + w.y * x0.y + w.z * x0.z + w.w * x0.w;
            a1 += w.x * x1.x + w.y * x1.y + w.z * x1.z + w.w * x1.w;
            a2 += w.x * x2.x + w.y * x2.y + w.z * x2.z + w.w * x2.w;
            a3 += w.x * x3.x + w.y * x3.y + w.z * x3.z + w.w * x3.w;
        }
        float bi = bias[i];
        hout[0][i] = fmaxf(a0 + bi, 0.f);
        hout[1][i] = fmaxf(a1 + bi, 0.f);
        hout[2][i] = fmaxf(a2 + bi, 0.f);
        hout[3][i] = fmaxf(a3 + bi, 0.f);
    }
}

__global__ void __launch_bounds__(256, 1)
k_mlp(const float* __restrict__ W0, const float* __restrict__ b0,
      const float* __restrict__ W1, const float* __restrict__ b1,
      const float* __restrict__ W2, const float* __restrict__ b2,
      const float* __restrict__ W3, const float* __restrict__ b3,
      float* __restrict__ out) {
    __shared__ float hA[4][D0];
    __shared__ float hB[4][D0];
    __shared__ float smScale[4];
    int tid = threadIdx.x;
    int bbase = blockIdx.x * 4;

    for (int idx = tid; idx < 4 * D0; idx += 256) {
        int bb = idx >> 9, j = idx & 511, t = j >> 6, r = j & 63;
        int g0 = (((bbase + bb) * TT + t) * 2 + 0) * RR + r;
        hA[bb][j] = g_gpart[g0] + g_gpart[g0 + RR];
    }
    __syncthreads();

    int lane = tid & 31, wrp = tid >> 5;
    if (wrp < 4) {
        float ss = 0.f;
        for (int i = lane; i < D0; i += 32) { float v = hA[wrp][i]; ss += v * v; }
#pragma unroll
        for (int o = 16; o > 0; o >>= 1) ss += __shfl_xor_sync(0xffffffffu, ss, o);
        if (lane == 0) smScale[wrp] = 1.f / fmaxf(sqrtf(ss), 1e-12f);
    }
    __syncthreads();
    for (int idx = tid; idx < 4 * D0; idx += 256) {
        int bb = idx >> 9;
        hA[bb][idx & 511] *= smScale[bb];
    }
    __syncthreads();

    mlp_layer(hA, hB, W0, b0, 512, 512, tid); __syncthreads();
    mlp_layer(hB, hA, W1, b1, 512, 512, tid); __syncthreads();
    mlp_layer(hA, hB, W2, b2, 512, 256, tid); __syncthreads();

    for (int i = tid; i < 128; i += 256) {
        const float4* wr = (const float4*)(W3 + (size_t)i * 256);
        float a0 = 0.f, a1 = 0.f, a2 = 0.f, a3 = 0.f;
#pragma unroll 4
        for (int k4 = 0; k4 < 64; k4++) {
            float4 w = __ldg(&wr[k4]);
            float4 x0 = *(const float4*)&hB[0][k4 * 4];
            float4 x1 = *(const float4*)&hB[1][k4 * 4];
            float4 x2 = *(const float4*)&hB[2][k4 * 4];
            float4 x3 = *(const float4*)&hB[3][k4 * 4];
            a0 += w.x * x0.x + w.y * x0.y + w.z * x0.z + w.w * x0.w;
            a1 += w.x * x1.x + w.y * x1.y + w.z * x1.z + w.w * x1.w;
            a2 += w.x * x2.x + w.y * x2.y + w.z * x2.z + w.w * x2.w;
            a3 += w.x * x3.x + w.y * x3.y + w.z * x3.z + w.w * x3.w;
        }
        float bi = b3[i];
        out[(bbase + 0) * 128 + i] = a0 + bi;
        out[(bbase + 1) * 128 + i] = a1 + bi;
        out[(bbase + 2) * 128 + i] = a2 + bi;
        out[(bbase + 3) * 128 + i] = a3 + bi;
    }
}

// ---------------------------------------------------------------------------
// launch
// ---------------------------------------------------------------------------
extern "C" void kernel_launch(void* const* d_in, const int* in_sizes, int n_in,
                              void* d_out, int out_size) {
    const float* attr = (const float*)d_in[0];
    const int*   adj  = (const int*)d_in[1];
    const float* W    = (const float*)d_in[2];
    const float* Wv   = (const float*)d_in[3];
    const float* Ww   = (const float*)d_in[4];
    const float* Wg   = (const float*)d_in[5];
    const float* W0   = (const float*)d_in[6];
    const float* b0   = (const float*)d_in[7];
    const float* W1   = (const float*)d_in[8];
    const float* b1   = (const float*)d_in[9];
    const float* W2   = (const float*)d_in[10];
    const float* b2   = (const float*)d_in[11];
    const float* W3   = (const float*)d_in[12];
    const float* b3   = (const float*)d_in[13];
    float* out = (float*)d_out;

    cudaFuncSetAttribute(k_F1,   cudaFuncAttributeMaxDynamicSharedMemorySize, SM_F1);
    cudaFuncSetAttribute(k_iter, cudaFuncAttributeMaxDynamicSharedMemorySize, SM_ITER);

    k_pack_adj<<<dim3(32, 64), 256>>>(adj);
    k_M<<<64, 256>>>(Wv, W);
    k_F1<<<dim3(2, 64), 256, SM_F1>>>(attr, Wg);
    for (int t = 1; t < TT; t++)
        k_iter<<<dim3(2, 64), 512, SM_ITER>>>(Ww, Wg, t);
    k_mlp<<<16, 256>>>(W0, b0, W1, b1, W2, b2, W3, b3, out);
}

// round 11
// speedup vs baseline: 1.3294x; 1.3191x over previous
#include <cuda_runtime.h>
#include <math.h>

// Problem constants
#define BB   64      // batch
#define NN   512     // nodes
#define RR   64      // r' (RP)
#define FEATD 256    // node features
#define EMBD 128     // embedding
#define TT   8       // MAX_WALK_LEN
#define D0   512     // MLP width (RR*TT)

#define LOG2E 1.4426950408889634f

// ---------------------------------------------------------------------------
// Device scratch (no cudaMalloc allowed)
// ---------------------------------------------------------------------------
__device__ float        g_M[RR * FEATD];             // Wv @ W  [64,256]
__device__ float        g_F1[BB * RR * NN];          // F1      [B,64,512]
__device__ float        g_FnA[BB * RR * NN];         // ping
__device__ float        g_FnB[BB * RR * NN];         // pong
__device__ unsigned int g_adjp[BB * NN * (NN / 32)]; // packed adjacency bits [B][m][n/32]
__device__ float        g_gpart[BB * TT * 2 * RR];   // gate partials per (b,t,tile,r)

// ---------------------------------------------------------------------------
// K0: pack adjacency: bit n of g_adjp[b][m][w] = (adj[b][n][m] != 0), n = w*32+j
// ---------------------------------------------------------------------------
__global__ void k_pack_adj(const int* __restrict__ adj) {
    int b  = blockIdx.y;
    int w  = blockIdx.x & 15;
    int mt = blockIdx.x >> 4;
    int m  = mt * 256 + threadIdx.x;
    const int* base = adj + ((size_t)b * NN + w * 32) * NN + m;
    unsigned int word = 0;
#pragma unroll
    for (int j = 0; j < 32; j++)
        word |= (base[j * NN] != 0 ? 1u : 0u) << j;
    g_adjp[(b * NN + m) * (NN / 32) + w] = word;
}

// ---------------------------------------------------------------------------
// K1: M = Wv[64,128] @ W[128,256]
// ---------------------------------------------------------------------------
__global__ void k_M(const float* __restrict__ Wv, const float* __restrict__ W) {
    int idx = blockIdx.x * 256 + threadIdx.x;
    int r = idx >> 8, c = idx & 255;
    float a = 0.f;
#pragma unroll 4
    for (int e = 0; e < EMBD; e++)
        a += Wv[r * EMBD + e] * W[e * FEATD + c];
    g_M[r * FEATD + c] = a;
}

// ---------------------------------------------------------------------------
// K2: F1[b,:,m] = sigmoid(M @ attr[b,m,:]) ; also gate_0 partials
// grid (2, 64), block 256, one column per thread
// ---------------------------------------------------------------------------
#define SM_F1 ((RR * FEATD + RR * RR + 8 * RR) * 4)

__global__ void __launch_bounds__(256, 1)
k_F1(const float* __restrict__ attr, const float* __restrict__ Wg) {
    extern __shared__ float sm[];
    float* smM  = sm;                   // [64][256]
    float* smWg = sm + RR * FEATD;      // [64][64]
    float* smG  = smWg + RR * RR;       // [8][64]

    int b = blockIdx.y, tile = blockIdx.x, tid = threadIdx.x;

    {
        const float4* s = (const float4*)g_M;
        float4* d = (float4*)smM;
        for (int i = tid; i < RR * FEATD / 4; i += 256) d[i] = s[i];
        const float4* s2 = (const float4*)Wg;
        float4* d2 = (float4*)smWg;
        for (int i = tid; i < RR * RR / 4; i += 256) d2[i] = s2[i];
    }
    __syncthreads();

    int m = tile * 256 + tid;
    float acc[RR];
#pragma unroll
    for (int r = 0; r < RR; r++) acc[r] = 0.f;

    const float4* arow = (const float4*)(attr + ((size_t)b * NN + m) * FEATD);
#pragma unroll 1
    for (int k4 = 0; k4 < FEATD / 4; k4++) {
        float4 a = __ldg(&arow[k4]);
        const float4* mc = (const float4*)smM + k4;
#pragma unroll
        for (int r = 0; r < RR; r++) {
            float4 w = mc[r * (FEATD / 4)];
            acc[r] += a.x * w.x + a.y * w.y + a.z * w.z + a.w * w.w;
        }
    }

#pragma unroll
    for (int r = 0; r < RR; r++) {
        float v = 1.f / (1.f + __expf(-acc[r]));
        acc[r] = v;
        g_F1[((size_t)b * RR + r) * NN + m] = v;
    }

    int lane = tid & 31, wrp = tid >> 5;
#pragma unroll 1
    for (int r = 0; r < RR; r++) {
        const float4* wr = (const float4*)(smWg + r * RR);
        float g = 0.f;
#pragma unroll
        for (int s4 = 0; s4 < RR / 4; s4++) {
            float4 w = wr[s4];
            g += w.x * acc[s4 * 4] + w.y * acc[s4 * 4 + 1] +
                 w.z * acc[s4 * 4 + 2] + w.w * acc[s4 * 4 + 3];
        }
        g = 1.f / (1.f + __expf(-g));
#pragma unroll
        for (int o = 16; o > 0; o >>= 1) g += __shfl_xor_sync(0xffffffffu, g, o);
        if (lane == 0) smG[wrp * RR + r] = g;
    }
    __syncthreads();
    if (tid < RR) {
        float tot = 0.f;
#pragma unroll
        for (int w = 0; w < 8; w++) tot += smG[w * RR + tid];
        g_gpart[((b * TT + 0) * 2 + tile) * RR + tid] = tot;
    }
}

// ---------------------------------------------------------------------------
// K3: one walk iteration (masked attention) + gate  [R7 core, measured best]
// grid (2, 64), block 512. Two threads per column: thread s owns interleaved
// rows r = s + 2i (i < 32). Row stride 520 (== 8 mod 32): the two slices'
// LDS.128 addresses land in disjoint bank quads -> conflict-free broadcast.
// 8 keys per chunk, score pass packed fma.rn.f32x2, accumulate scalar.
// Direct exp via ex2.approx with log2(e) FOLDED INTO wwf (numerically
// identical to __expf(S): ex2(S*log2e) = e^S); masked keys get p = 0.
// ---------------------------------------------------------------------------
#define RSTRIDE 520
#define WSTRIDE 72
#define SM_ITER ((64 * RSTRIDE + 64 * WSTRIDE + RR * RR + 16 * RR) * 4 + 256 * 16 * 4)

__global__ void __launch_bounds__(512, 1)
k_iter(const float* __restrict__ Ww, const float* __restrict__ Wg, int t) {
    extern __shared__ float sm[];
    float*        smFnP = sm;                                // [64][520]
    float*        smWwP = sm + 64 * RSTRIDE;                 // [sp][72] permuted
    float*        smWg  = smWwP + 64 * WSTRIDE;              // [r][s]
    unsigned int* smAdj = (unsigned int*)(smWg + RR * RR);   // [256][16]
    float*        smG   = (float*)(smAdj + 256 * 16);        // [16][64]

    int b = blockIdx.y, tile = blockIdx.x, tid = threadIdx.x;

    const float* Fn_in  = (t == 1) ? g_F1 : ((t & 1) ? g_FnB : g_FnA);
    float*       Fn_out = (t & 1) ? g_FnA : g_FnB;

    {
        const float4* src = (const float4*)(Fn_in + (size_t)b * RR * NN);
        for (int idx = tid; idx < RR * NN / 4; idx += 512) {
            int row = idx >> 7, c4 = idx & 127;
            *((float4*)(smFnP + row * RSTRIDE) + c4) = src[idx];
        }
        // permuted Ww for interleaved slices: smWwP[sp*72 + (r&1)*36 + (r>>1)] = Ww[r][sp]
        for (int i = tid; i < RR * RR; i += 512) {
            int r = i >> 6, sp = i & 63;
            smWwP[sp * WSTRIDE + (r & 1) * 36 + (r >> 1)] = Ww[i];
        }
        const float4* s3 = (const float4*)Wg;
        float4* d3 = (float4*)smWg;
        for (int i = tid; i < RR * RR / 4; i += 512) d3[i] = s3[i];
        const uint4* s4p = (const uint4*)(g_adjp + ((size_t)b * NN + tile * 256) * 16);
        uint4* d4 = (uint4*)smAdj;
        for (int i = tid; i < 256 * 16 / 4; i += 512) d4[i] = s4p[i];
    }
    __syncthreads();

    int s  = tid & 1;          // slice: rows r = s + 2i
    int ml = tid >> 1;         // local column 0..255
    int m  = tile * 256 + ml;

    // ---- wwf[i] = sum_s' Ww[s+2i][s'] * Fn[s'][m], then fold in log2(e)
    float wwf[32];
#pragma unroll
    for (int i = 0; i < 32; i++) wwf[i] = 0.f;
#pragma unroll 1
    for (int sp = 0; sp < 64; sp++) {
        float fs = smFnP[sp * RSTRIDE + m];
        const float4* wq = (const float4*)(smWwP + sp * WSTRIDE + s * 36);
#pragma unroll
        for (int q = 0; q < 8; q++) {
            float4 w = wq[q];
            wwf[q*4+0] += w.x * fs;
            wwf[q*4+1] += w.y * fs;
            wwf[q*4+2] += w.z * fs;
            wwf[q*4+3] += w.w * fs;
        }
    }
#pragma unroll
    for (int i = 0; i < 32; i++) wwf[i] *= LOG2E;   // ex2(S*log2e) == e^S

    // ---- masked attention, 8 keys per chunk, direct ex2
    float acc[32];
#pragma unroll
    for (int i = 0; i < 32; i++) acc[i] = 0.f;
    float dn = 0.f;
    unsigned int aw = 0;
    const unsigned int* myadj = smAdj + ml * 16;
    const ulonglong2* frows = (const ulonglong2*)(smFnP + s * RSTRIDE);

#pragma unroll 1
    for (int n0 = 0; n0 < NN; n0 += 8) {
        if ((n0 & 31) == 0) aw = myadj[n0 >> 5];

        const ulonglong2* fr = frows + (n0 >> 2);   // rows s+2i step 260 ul2

        // packed partial scores for this slice: s01, s23, s45, s67
        unsigned long long s01 = 0ull, s23 = 0ull, s45 = 0ull, s67 = 0ull;
#pragma unroll
        for (int i = 0; i < 32; i++) {
            ulonglong2 fa = fr[i * 260];       // keys n0..n3
            ulonglong2 fb = fr[i * 260 + 1];   // keys n4..n7
            unsigned long long w2;
            asm("mov.b64 %0, {%1, %1};" : "=l"(w2) : "f"(wwf[i]));
            asm("fma.rn.f32x2 %0, %1, %2, %0;" : "+l"(s01) : "l"(fa.x), "l"(w2));
            asm("fma.rn.f32x2 %0, %1, %2, %0;" : "+l"(s23) : "l"(fa.y), "l"(w2));
            asm("fma.rn.f32x2 %0, %1, %2, %0;" : "+l"(s45) : "l"(fb.x), "l"(w2));
            asm("fma.rn.f32x2 %0, %1, %2, %0;" : "+l"(s67) : "l"(fb.y), "l"(w2));
        }
        // combine with pair partner (other slice) — batched for ILP
        {
            unsigned long long o0 = __shfl_xor_sync(0xffffffffu, s01, 1);
            unsigned long long o1 = __shfl_xor_sync(0xffffffffu, s23, 1);
            unsigned long long o2 = __shfl_xor_sync(0xffffffffu, s45, 1);
            unsigned long long o3 = __shfl_xor_sync(0xffffffffu, s67, 1);
            asm("add.rn.f32x2 %0, %0, %1;" : "+l"(s01) : "l"(o0));
            asm("add.rn.f32x2 %0, %0, %1;" : "+l"(s23) : "l"(o1));
            asm("add.rn.f32x2 %0, %0, %1;" : "+l"(s45) : "l"(o2));
            asm("add.rn.f32x2 %0, %0, %1;" : "+l"(s67) : "l"(o3));
        }
        float s0, s1, s2, s3, s4, s5, s6, s7;
        asm("mov.b64 {%0, %1}, %2;" : "=f"(s0), "=f"(s1) : "l"(s01));
        asm("mov.b64 {%0, %1}, %2;" : "=f"(s2), "=f"(s3) : "l"(s23));
        asm("mov.b64 {%0, %1}, %2;" : "=f"(s4), "=f"(s5) : "l"(s45));
        asm("mov.b64 {%0, %1}, %2;" : "=f"(s6), "=f"(s7) : "l"(s67));

        unsigned int bits = aw >> (n0 & 31);
        float e0, e1, e2, e3, e4, e5, e6, e7;
        asm("ex2.approx.f32 %0, %1;" : "=f"(e0) : "f"(s0));
        asm("ex2.approx.f32 %0, %1;" : "=f"(e1) : "f"(s1));
        asm("ex2.approx.f32 %0, %1;" : "=f"(e2) : "f"(s2));
        asm("ex2.approx.f32 %0, %1;" : "=f"(e3) : "f"(s3));
        asm("ex2.approx.f32 %0, %1;" : "=f"(e4) : "f"(s4));
        asm("ex2.approx.f32 %0, %1;" : "=f"(e5) : "f"(s5));
        asm("ex2.approx.f32 %0, %1;" : "=f"(e6) : "f"(s6));
        asm("ex2.approx.f32 %0, %1;" : "=f"(e7) : "f"(s7));
        float p0 = (bits & 1u)   ? e0 : 0.f;
        float p1 = (bits & 2u)   ? e1 : 0.f;
        float p2 = (bits & 4u)   ? e2 : 0.f;
        float p3 = (bits & 8u)   ? e3 : 0.f;
        float p4 = (bits & 16u)  ? e4 : 0.f;
        float p5 = (bits & 32u)  ? e5 : 0.f;
        float p6 = (bits & 64u)  ? e6 : 0.f;
        float p7 = (bits & 128u) ? e7 : 0.f;
        dn += ((p0 + p1) + (p2 + p3)) + ((p4 + p5) + (p6 + p7));

#pragma unroll
        for (int i = 0; i < 32; i++) {
            const float4* row = (const float4*)(smFnP + (s + 2*i) * RSTRIDE + n0);
            float4 a = row[0], b4 = row[1];
            acc[i] += a.x * p0 + a.y * p1 + a.z * p2 + a.w * p3 +
                      b4.x * p4 + b4.y * p5 + b4.z * p6 + b4.w * p7;
        }
    }

    // ---- epilogue: scale, multiply by F1, write global + restage to smem
    float inv = 1.f / dn;
    __syncthreads();   // all reads of old smFnP complete before restaging
    const float* f1base = g_F1 + (size_t)b * RR * NN;
    float*       outb   = Fn_out + (size_t)b * RR * NN;
#pragma unroll
    for (int i = 0; i < 32; i++) {
        int r = s + 2 * i;
        float v = acc[i] * inv * f1base[r * NN + m];
        outb[r * NN + m] = v;
        smFnP[r * RSTRIDE + ml] = v;
    }
    __syncthreads();

    // ---- gate_t = sum_m sigmoid(Wg @ Fn_new[:,m])  (validated structure)
    int rb = (tid & 1) * 32;      // r-half for the gate dot
    float f[32];
#pragma unroll
    for (int i = 0; i < 32; i++) f[i] = smFnP[(rb + i) * RSTRIDE + ml];

    int lane = tid & 31, wrp = tid >> 5;
#pragma unroll 1
    for (int r = 0; r < RR; r++) {
        const float4* wr = (const float4*)(smWg + r * RR + rb);
        float g = 0.f;
#pragma unroll
        for (int s4 = 0; s4 < 8; s4++) {
            float4 w = wr[s4];
            g += w.x * f[s4*4] + w.y * f[s4*4+1] +
                 w.z * f[s4*4+2] + w.w * f[s4*4+3];
        }
        g += __shfl_xor_sync(0xffffffffu, g, 1);       // full dot for this column
        g = 1.f / (1.f + __expf(-g));
#pragma unroll
        for (int o = 2; o < 32; o <<= 1) g += __shfl_xor_sync(0xffffffffu, g, o);
        if (lane == 0) smG[wrp * RR + r] = g;          // 16 distinct columns per warp
    }
    __syncthreads();
    if (tid < RR) {
        float tot = 0.f;
#pragma unroll
        for (int w = 0; w < 16; w++) tot += smG[w * RR + tid];
        g_gpart[((b * TT + t) * 2 + tile) * RR + tid] = tot;
    }
}

// ---------------------------------------------------------------------------
// K4: assemble fT, L2-normalize, 4-layer MLP. grid 16 (4 batches/CTA), block 256
// ---------------------------------------------------------------------------
__device__ __forceinline__ void mlp_layer(const float (*hin)[D0], float (*hout)[D0],
                                          const float* __restrict__ W,
                                          const float* __restrict__ bias,
                                          int Din, int Dout, int tid) {
    for (int i = tid; i < Dout; i += 256) {
        const float4* wr = (const float4*)(W + (size_t)i * Din);
        float a0 = 0.f, a1 = 0.f, a2 = 0.f, a3 = 0.f;
#pragma unroll 4
        for (int k4 = 0; k4 < Din / 4; k4++) {
            float4 w = __ldg(&wr[k4]);
            float4 x0 = *(const float4*)&hin[0][k4 * 4];
            float4 x1 = *(const float4*)&hin[1][k4 * 4];
            float4 x2 = *(const float4*)&hin[2][k4 * 4];
            float4 x3 = *(const float4*)&hin[3][k4 * 4];
            a0 += w.x * x0.x + w.y * x0.y + w.z * x0.z + w.w * x0.w;
            a1 += w.x * x1.x + w.y * x1.y + w.z * x1.z + w.w * x1.w;
            a2 += w.x * x2.x + w.y * x2.y + w.z * x2.z + w.w * x2.w;
            a3 += w.x * x3.x + w.y * x3.y + w.z * x3.z + w.w * x3.w;
        }
        float bi = bias[i];
        hout[0][i] = fmaxf(a0 + bi, 0.f);
        hout[1][i] = fmaxf(a1 + bi, 0.f);
        hout[2][i] = fmaxf(a2 + bi, 0.f);
        hout[3][i] = fmaxf(a3 + bi, 0.f);
    }
}

__global__ void __launch_bounds__(256, 1)
k_mlp(const float* __restrict__ W0, const float* __restrict__ b0,
      const float* __restrict__ W1, const float* __restrict__ b1,
      const float* __restrict__ W2, const float* __restrict__ b2,
      const float* __restrict__ W3, const float* __restrict__ b3,
      float* __restrict__ out) {
    __shared__ float hA[4][D0];
    __shared__ float hB[4][D0];
    __shared__ float smScale[4];
    int tid = threadIdx.x;
    int bbase = blockIdx.x * 4;

    for (int idx = tid; idx < 4 * D0; idx += 256) {
        int bb = idx >> 9, j = idx & 511, t = j >> 6, r = j & 63;
        int g0 = (((bbase + bb) * TT + t) * 2 + 0) * RR + r;
        hA[bb][j] = g_gpart[g0] + g_gpart[g0 + RR];
    }
    __syncthreads();

    int lane = tid & 31, wrp = tid >> 5;
    if (wrp < 4) {
        float ss = 0.f;
        for (int i = lane; i < D0; i += 32) { float v = hA[wrp][i]; ss += v * v; }
#pragma unroll
        for (int o = 16; o > 0; o >>= 1) ss += __shfl_xor_sync(0xffffffffu, ss, o);
        if (lane == 0) smScale[wrp] = 1.f / fmaxf(sqrtf(ss), 1e-12f);
    }
    __syncthreads();
    for (int idx = tid; idx < 4 * D0; idx += 256) {
        int bb = idx >> 9;
        hA[bb][idx & 511] *= smScale[bb];
    }
    __syncthreads();

    mlp_layer(hA, hB, W0, b0, 512, 512, tid); __syncthreads();
    mlp_layer(hB, hA, W1, b1, 512, 512, tid); __syncthreads();
    mlp_layer(hA, hB, W2, b2, 512, 256, tid); __syncthreads();

    for (int i = tid; i < 128; i += 256) {
        const float4* wr = (const float4*)(W3 + (size_t)i * 256);
        float a0 = 0.f, a1 = 0.f, a2 = 0.f, a3 = 0.f;
#pragma unroll 4
        for (int k4 = 0; k4 < 64; k4++) {
            float4 w = __ldg(&wr[k4]);
            float4 x0 = *(const float4*)&hB[0][k4 * 4];
            float4 x1 = *(const float4*)&hB[1][k4 * 4];
            float4 x2 = *(const float4*)&hB[2][k4 * 4];
            float4 x3 = *(const float4*)&hB[3][k4 * 4];
            a0 += w.x * x0.x + w.y * x0.y + w.z * x0.z + w.w * x0.w;
            a1 += w.x * x1.x + w.y * x1.y + w.z * x1.z + w.w * x1.w;
            a2 += w.x * x2.x + w.y * x2.y + w.z * x2.z + w.w * x2.w;
            a3 += w.x * x3.x + w.y * x3.y + w.z * x3.z + w.w * x3.w;
        }
        float bi = b3[i];
        out[(bbase + 0) * 128 + i] = a0 + bi;
        out[(bbase + 1) * 128 + i] = a1 + bi;
        out[(bbase + 2) * 128 + i] = a2 + bi;
        out[(bbase + 3) * 128 + i] = a3 + bi;
    }
}

// ---------------------------------------------------------------------------
// launch
// ---------------------------------------------------------------------------
extern "C" void kernel_launch(void* const* d_in, const int* in_sizes, int n_in,
                              void* d_out, int out_size) {
    const float* attr = (const float*)d_in[0];
    const int*   adj  = (const int*)d_in[1];
    const float* W    = (const float*)d_in[2];
    const float* Wv   = (const float*)d_in[3];
    const float* Ww   = (const float*)d_in[4];
    const float* Wg   = (const float*)d_in[5];
    const float* W0   = (const float*)d_in[6];
    const float* b0   = (const float*)d_in[7];
    const float* W1   = (const float*)d_in[8];
    const float* b1   = (const float*)d_in[9];
    const float* W2   = (const float*)d_in[10];
    const float* b2   = (const float*)d_in[11];
    const float* W3   = (const float*)d_in[12];
    const float* b3   = (const float*)d_in[13];
    float* out = (float*)d_out;

    cudaFuncSetAttribute(k_F1,   cudaFuncAttributeMaxDynamicSharedMemorySize, SM_F1);
    cudaFuncSetAttribute(k_iter, cudaFuncAttributeMaxDynamicSharedMemorySize, SM_ITER);

    k_pack_adj<<<dim3(32, 64), 256>>>(adj);
    k_M<<<64, 256>>>(Wv, W);
    k_F1<<<dim3(2, 64), 256, SM_F1>>>(attr, Wg);
    for (int t = 1; t < TT; t++)
        k_iter<<<dim3(2, 64), 512, SM_ITER>>>(Ww, Wg, t);
    k_mlp<<<16, 256>>>(W0, b0, W1, b1, W2, b2, W3, b3, out);
}